// round 3
// baseline (speedup 1.0000x reference)
#include <cuda_runtime.h>
#include <math.h>

#define N_NODES  20000
#define N_EDGES  320000
#define NUM_G    64
#define D1       256
#define D2       128

// ---------------- scratch (device globals; no allocation allowed) -------------
__device__ float g_dinv[N_NODES];
__device__ int   g_cnt[N_NODES];
__device__ int   g_cursor[N_NODES];
__device__ int   g_rowstart[N_NODES + 1];
__device__ int   g_csrsrc[N_EDGES];
__device__ float g_h1[(size_t)N_NODES * D1];   // x @ W1
__device__ float g_a1[(size_t)N_NODES * D1];   // relu(Ahat h1 + b1)
__device__ float g_h2[(size_t)N_NODES * D2];   // a1 @ W2
__device__ float g_pool[NUM_G * D2];
__device__ float g_pcnt[NUM_G];

// ---------------- init ----------------
__global__ void k_init() {
    int i = blockIdx.x * blockDim.x + threadIdx.x;
    if (i < N_NODES) { g_cnt[i] = 0; g_cursor[i] = 0; }
    if (i < NUM_G * D2) g_pool[i] = 0.0f;
    if (i < NUM_G) g_pcnt[i] = 0.0f;
}

// ---------------- degree histogram over dst (edge_index is int32!) ----------------
__global__ void k_cnt(const int* __restrict__ ei) {
    int e = blockIdx.x * blockDim.x + threadIdx.x;
    if (e < N_EDGES) atomicAdd(&g_cnt[ei[N_EDGES + e]], 1);
}

__global__ void k_dinv() {
    int i = blockIdx.x * blockDim.x + threadIdx.x;
    if (i < N_NODES) g_dinv[i] = rsqrtf((float)(g_cnt[i] + 1));  // +1 self loop
}

// ---------------- single-block exclusive scan over g_cnt -> g_rowstart ----------------
__global__ void k_scan() {
    __shared__ int tmp[1024];
    __shared__ int carry_s;
    int tid = threadIdx.x;
    if (tid == 0) { carry_s = 0; g_rowstart[0] = 0; }
    __syncthreads();
    for (int base = 0; base < N_NODES; base += 1024) {
        int i = base + tid;
        int v = (i < N_NODES) ? g_cnt[i] : 0;
        tmp[tid] = v;
        __syncthreads();
        for (int off = 1; off < 1024; off <<= 1) {
            int t = (tid >= off) ? tmp[tid - off] : 0;
            __syncthreads();
            if (tid >= off) tmp[tid] += t;
            __syncthreads();
        }
        int cbase = carry_s;
        if (i < N_NODES) g_rowstart[i + 1] = cbase + tmp[tid];
        __syncthreads();
        if (tid == 1023) carry_s = cbase + tmp[1023];
        __syncthreads();
    }
}

// ---------------- CSR fill ----------------
__global__ void k_fill(const int* __restrict__ ei) {
    int e = blockIdx.x * blockDim.x + threadIdx.x;
    if (e < N_EDGES) {
        int d = ei[N_EDGES + e];
        int pos = atomicAdd(&g_cursor[d], 1);
        g_csrsrc[g_rowstart[d] + pos] = ei[e];
    }
}

// ---------------- fp32 SGEMM writing to device-global scratch ----------------
// LAYER 0: C=g_h1 = A(x)[20000,256] @ B(W1)[256,256]
// LAYER 1: C=g_h2 = g_a1[20000,256] @ B(W2)[256,128]
// BM=128, BN=128, BK=8, 256 threads, 8x8 per thread.
template<int LAYER>
__global__ __launch_bounds__(256) void sgemm_k(const float* __restrict__ Ain,
                                               const float* __restrict__ B) {
    constexpr int K = 256;
    constexpr int N = (LAYER == 0) ? 256 : 128;
    const float* A = (LAYER == 0) ? Ain : (const float*)g_a1;
    float* C = (LAYER == 0) ? (float*)g_h1 : (float*)g_h2;
    constexpr int M = N_NODES;

    __shared__ float As[8][128];
    __shared__ float Bs[8][128];
    int tid  = threadIdx.x;
    int row0 = blockIdx.x * 128;
    int col0 = blockIdx.y * 128;
    int tx = tid & 15, ty = tid >> 4;

    float acc[8][8];
    #pragma unroll
    for (int i = 0; i < 8; i++)
        #pragma unroll
        for (int j = 0; j < 8; j++) acc[i][j] = 0.0f;

    int ar = tid >> 1;            // 0..127
    int ak = (tid & 1) * 4;       // 0 or 4
    int br = tid >> 5;            // 0..7
    int bc = (tid & 31) * 4;      // 0..124

    for (int k0 = 0; k0 < K; k0 += 8) {
        float4 av = make_float4(0.f, 0.f, 0.f, 0.f);
        if (row0 + ar < M)
            av = *(const float4*)&A[(size_t)(row0 + ar) * K + k0 + ak];
        float4 bv = *(const float4*)&B[(size_t)(k0 + br) * N + col0 + bc];
        __syncthreads();
        As[ak + 0][ar] = av.x; As[ak + 1][ar] = av.y;
        As[ak + 2][ar] = av.z; As[ak + 3][ar] = av.w;
        *(float4*)&Bs[br][bc] = bv;
        __syncthreads();
        #pragma unroll
        for (int kk = 0; kk < 8; kk++) {
            float a[8], b[8];
            #pragma unroll
            for (int i = 0; i < 8; i++) a[i] = As[kk][ty * 8 + i];
            #pragma unroll
            for (int j = 0; j < 8; j++) b[j] = Bs[kk][tx * 8 + j];
            #pragma unroll
            for (int i = 0; i < 8; i++)
                #pragma unroll
                for (int j = 0; j < 8; j++) acc[i][j] += a[i] * b[j];
        }
    }
    #pragma unroll
    for (int i = 0; i < 8; i++) {
        int r = row0 + ty * 8 + i;
        if (r < M) {
            float4 v0 = make_float4(acc[i][0], acc[i][1], acc[i][2], acc[i][3]);
            float4 v1 = make_float4(acc[i][4], acc[i][5], acc[i][6], acc[i][7]);
            *(float4*)&C[(size_t)r * N + col0 + tx * 8]     = v0;
            *(float4*)&C[(size_t)r * N + col0 + tx * 8 + 4] = v1;
        }
    }
}

// ---------------- aggregation ----------------
// out[v] = relu(dinv[v]*(dinv[v]*h[v] + sum_s dinv[s]*h[s]) + b)
// LAYER 0: h=g_h1 (DIM=256), out=g_a1.
// LAYER 1: h=g_h2 (DIM=128), fused mean-pool atomics instead of store.
template<int LAYER>
__global__ void agg_kernel(const float* __restrict__ bias,
                           const int* __restrict__ batch) {
    constexpr int DIM = (LAYER == 0) ? D1 : D2;
    const float* h = (LAYER == 0) ? (const float*)g_h1 : (const float*)g_h2;
    int w    = (blockIdx.x * blockDim.x + threadIdx.x) >> 5;
    int lane = threadIdx.x & 31;
    if (w >= N_NODES) return;
    constexpr int R = DIM / 32;
    float dv = g_dinv[w];
    float acc[R];
    const float* hv = h + (size_t)w * DIM;
    #pragma unroll
    for (int j = 0; j < R; j++) acc[j] = dv * hv[j * 32 + lane];
    int e0 = g_rowstart[w], e1 = g_rowstart[w + 1];
    for (int e = e0; e < e1; e++) {
        int s = g_csrsrc[e];
        float ws = g_dinv[s];
        const float* hs = h + (size_t)s * DIM;
        #pragma unroll
        for (int j = 0; j < R; j++) acc[j] += ws * hs[j * 32 + lane];
    }
    if (LAYER == 1) {
        int g = batch[w];
        #pragma unroll
        for (int j = 0; j < R; j++) {
            float v = fmaxf(dv * acc[j] + bias[j * 32 + lane], 0.0f);
            atomicAdd(&g_pool[g * DIM + j * 32 + lane], v);
        }
        if (lane == 0) atomicAdd(&g_pcnt[g], 1.0f);
    } else {
        #pragma unroll
        for (int j = 0; j < R; j++) {
            float v = fmaxf(dv * acc[j] + bias[j * 32 + lane], 0.0f);
            g_a1[(size_t)w * DIM + j * 32 + lane] = v;
        }
    }
}

// ---------------- MLP head: per-graph mean -> 128->64 relu -> 64->1 sigmoid ----------------
__global__ void k_head(const float* __restrict__ Wl1, const float* __restrict__ bl1,
                       const float* __restrict__ Wl2, const float* __restrict__ bl2,
                       float* __restrict__ out) {
    __shared__ float gv[128];
    __shared__ float hid[64];
    int g = blockIdx.x, t = threadIdx.x;
    float c = fmaxf(g_pcnt[g], 1.0f);
    gv[t] = g_pool[g * D2 + t] / c;
    __syncthreads();
    if (t < 64) {
        float s = bl1[t];
        #pragma unroll 4
        for (int k = 0; k < 128; k++) s += gv[k] * Wl1[k * 64 + t];
        hid[t] = fmaxf(s, 0.0f);
    }
    __syncthreads();
    if (t == 0) {
        float s = bl2[0];
        #pragma unroll 4
        for (int k = 0; k < 64; k++) s += hid[k] * Wl2[k];
        out[g] = 1.0f / (1.0f + expf(-s));
    }
}

// ---------------- launch ----------------
extern "C" void kernel_launch(void* const* d_in, const int* in_sizes, int n_in,
                              void* d_out, int out_size) {
    const float* x    = (const float*)d_in[0];
    const int*   ei   = (const int*)d_in[1];    // int32 (JAX x64 disabled)
    const int*   bat  = (const int*)d_in[2];    // int32
    const float* W1   = (const float*)d_in[3];
    const float* b1   = (const float*)d_in[4];
    const float* W2   = (const float*)d_in[5];
    const float* b2   = (const float*)d_in[6];
    const float* Wl1  = (const float*)d_in[7];
    const float* bl1  = (const float*)d_in[8];
    const float* Wl2  = (const float*)d_in[9];
    const float* bl2  = (const float*)d_in[10];
    float* out = (float*)d_out;

    k_init<<<(N_NODES + 255) / 256, 256>>>();
    k_cnt<<<(N_EDGES + 255) / 256, 256>>>(ei);
    k_dinv<<<(N_NODES + 255) / 256, 256>>>();
    k_scan<<<1, 1024>>>();
    k_fill<<<(N_EDGES + 255) / 256, 256>>>(ei);

    // layer 1: h1 = x @ W1 ; a1 = relu(Ahat h1 + b1)
    {
        dim3 grid((N_NODES + 127) / 128, D1 / 128);
        sgemm_k<0><<<grid, 256>>>(x, W1);
    }
    agg_kernel<0><<<(N_NODES * 32 + 255) / 256, 256>>>(b1, nullptr);

    // layer 2: h2 = a1 @ W2 ; pool(relu(Ahat h2 + b2))
    {
        dim3 grid((N_NODES + 127) / 128, D2 / 128);
        sgemm_k<1><<<grid, 256>>>(nullptr, W2);
    }
    agg_kernel<1><<<(N_NODES * 32 + 255) / 256, 256>>>(b2, bat);

    k_head<<<NUM_G, 128>>>(Wl1, bl1, Wl2, bl2, out);
}

// round 4
// speedup vs baseline: 1.7076x; 1.7076x over previous
#include <cuda_runtime.h>
#include <math.h>
#include <stdint.h>

#define N_NODES  20000
#define N_EDGES  320000
#define NUM_G    64
#define D1       256
#define D2       128

// ---------------- scratch (device globals) -------------
__device__ float g_dinv[N_NODES];
__device__ int   g_cnt[N_NODES];
__device__ int   g_cursor[N_NODES];
__device__ int   g_rowstart[N_NODES + 1];
__device__ int   g_csrsrc[N_EDGES];
__device__ float g_h1[(size_t)N_NODES * D1];   // x @ W1
__device__ float g_a1[(size_t)N_NODES * D1];   // relu(Ahat h1 + b1)
__device__ float g_h2[(size_t)N_NODES * D2];   // a1 @ W2
__device__ float g_pool[NUM_G * D2];
__device__ float g_pcnt[NUM_G];

// ---------------- init ----------------
__global__ void k_init() {
    int i = blockIdx.x * blockDim.x + threadIdx.x;
    if (i < N_NODES) { g_cnt[i] = 0; g_cursor[i] = 0; }
    if (i < NUM_G * D2) g_pool[i] = 0.0f;
    if (i < NUM_G) g_pcnt[i] = 0.0f;
}

// ---------------- degree histogram over dst (int32 indices) ----------------
__global__ void k_cnt(const int* __restrict__ ei) {
    int e = blockIdx.x * blockDim.x + threadIdx.x;
    if (e < N_EDGES) atomicAdd(&g_cnt[ei[N_EDGES + e]], 1);
}

// ---------------- fast single-pass scan (+ fused dinv) ----------------
// 1024 threads x 20 elems. Register prefix + shuffle scan; 2 barriers total.
__global__ __launch_bounds__(1024) void k_scan2() {
    constexpr int PER = 20;  // 1024*20 = 20480 >= 20000
    __shared__ int wsum[32];
    int tid = threadIdx.x, lane = tid & 31, wid = tid >> 5;
    int base = tid * PER;
    int v[PER];
    int s = 0;
    #pragma unroll
    for (int j = 0; j < PER; j++) {
        int i = base + j;
        int c = (i < N_NODES) ? g_cnt[i] : 0;
        if (i < N_NODES) g_dinv[i] = rsqrtf((float)(c + 1));  // +1 self loop
        v[j] = s;           // exclusive prefix within thread
        s += c;
    }
    // warp inclusive scan of thread totals
    int incl = s;
    #pragma unroll
    for (int off = 1; off < 32; off <<= 1) {
        int n = __shfl_up_sync(0xffffffffu, incl, off);
        if (lane >= off) incl += n;
    }
    if (lane == 31) wsum[wid] = incl;
    __syncthreads();
    if (wid == 0) {
        int w = wsum[lane];
        #pragma unroll
        for (int off = 1; off < 32; off <<= 1) {
            int n = __shfl_up_sync(0xffffffffu, w, off);
            if (lane >= off) w += n;
        }
        wsum[lane] = w;  // inclusive warp prefix
    }
    __syncthreads();
    int warpbase = (wid > 0) ? wsum[wid - 1] : 0;
    int thbase = warpbase + incl - s;   // exclusive prefix of this thread
    #pragma unroll
    for (int j = 0; j < PER; j++) {
        int i = base + j;
        if (i < N_NODES) g_rowstart[i] = thbase + v[j];
    }
    if (tid == 0) g_rowstart[N_NODES] = N_EDGES;
}

// ---------------- CSR fill ----------------
__global__ void k_fill(const int* __restrict__ ei) {
    int e = blockIdx.x * blockDim.x + threadIdx.x;
    if (e < N_EDGES) {
        int d = ei[N_EDGES + e];
        int pos = atomicAdd(&g_cursor[d], 1);
        g_csrsrc[g_rowstart[d] + pos] = ei[e];
    }
}

// ---------------- tf32 tensor-core GEMM ----------------
__device__ __forceinline__ uint32_t f2tf32(float f) {
    uint32_t u;
    asm("cvt.rna.tf32.f32 %0, %1;" : "=r"(u) : "f"(f));
    return u;
}
__device__ __forceinline__ void mma8(float* acc, const uint32_t* a, const uint32_t* b) {
    asm volatile(
        "mma.sync.aligned.m16n8k8.row.col.f32.tf32.tf32.f32 "
        "{%0,%1,%2,%3},{%4,%5,%6,%7},{%8,%9},{%0,%1,%2,%3};"
        : "+f"(acc[0]), "+f"(acc[1]), "+f"(acc[2]), "+f"(acc[3])
        : "r"(a[0]), "r"(a[1]), "r"(a[2]), "r"(a[3]), "r"(b[0]), "r"(b[1]));
}

// C[M,N] = A[M,256] @ B[256,N]. BM=128, BN=64, BK=32, 256 threads (8 warps, 4x2).
// LAYER 0: A=x, C=g_h1, N=256. LAYER 1: A=g_a1, C=g_h2, N=128.
template<int LAYER>
__global__ __launch_bounds__(256) void gemm_tc(const float* __restrict__ Ain,
                                               const float* __restrict__ Bw) {
    constexpr int K = 256;
    constexpr int N = (LAYER == 0) ? 256 : 128;
    constexpr int M = N_NODES;
    const float* A = (LAYER == 0) ? Ain : (const float*)g_a1;
    float* C = (LAYER == 0) ? (float*)g_h1 : (float*)g_h2;

    // strides chosen for conflict-free fragment LDS:
    // As[m][k]: stride 36 -> bank(4r+c);  Bs[k][n]: stride 72 -> bank(8c+r)
    __shared__ uint32_t As[128 * 36];
    __shared__ uint32_t Bs[32 * 72];

    int tid = threadIdx.x, lane = tid & 31, warp = tid >> 5;
    int wm = warp & 3, wn = warp >> 2;
    int row0 = blockIdx.x * 128, col0 = blockIdx.y * 64;

    int am = tid >> 1, ah = (tid & 1) * 16;  // A: row am, k-offset ah..ah+15
    int bk = tid >> 4, bn = (tid & 15) * 4;  // B: rows bk & bk+16, cols bn..bn+3

    float acc[2][4][4];
    #pragma unroll
    for (int mt = 0; mt < 2; mt++)
        #pragma unroll
        for (int nt = 0; nt < 4; nt++)
            #pragma unroll
            for (int i = 0; i < 4; i++) acc[mt][nt][i] = 0.0f;

    float4 areg[4];
    float4 breg[2];
    bool aok = (row0 + am) < M;
    const float* aptr = A + (size_t)(row0 + am) * K + ah;
    const float* bptr = Bw + (size_t)bk * N + col0 + bn;

    auto ldg = [&](int k0) {
        #pragma unroll
        for (int j = 0; j < 4; j++)
            areg[j] = aok ? *(const float4*)(aptr + k0 + 4 * j)
                          : make_float4(0.f, 0.f, 0.f, 0.f);
        breg[0] = *(const float4*)(bptr + (size_t)k0 * N);
        breg[1] = *(const float4*)(bptr + (size_t)(k0 + 16) * N);
    };
    auto sts = [&]() {
        #pragma unroll
        for (int j = 0; j < 4; j++) {
            uint4 u = make_uint4(f2tf32(areg[j].x), f2tf32(areg[j].y),
                                 f2tf32(areg[j].z), f2tf32(areg[j].w));
            *(uint4*)&As[am * 36 + ah + 4 * j] = u;
        }
        uint4 u0 = make_uint4(f2tf32(breg[0].x), f2tf32(breg[0].y),
                              f2tf32(breg[0].z), f2tf32(breg[0].w));
        uint4 u1 = make_uint4(f2tf32(breg[1].x), f2tf32(breg[1].y),
                              f2tf32(breg[1].z), f2tf32(breg[1].w));
        *(uint4*)&Bs[bk * 72 + bn] = u0;
        *(uint4*)&Bs[(bk + 16) * 72 + bn] = u1;
    };
    int r = lane >> 2, c = lane & 3;
    auto compute = [&]() {
        #pragma unroll
        for (int kk = 0; kk < 32; kk += 8) {
            uint32_t af[2][4], bf[4][2];
            #pragma unroll
            for (int mt = 0; mt < 2; mt++) {
                int m0 = wm * 32 + mt * 16 + r;
                af[mt][0] = As[m0 * 36 + kk + c];
                af[mt][1] = As[(m0 + 8) * 36 + kk + c];
                af[mt][2] = As[m0 * 36 + kk + c + 4];
                af[mt][3] = As[(m0 + 8) * 36 + kk + c + 4];
            }
            #pragma unroll
            for (int nt = 0; nt < 4; nt++) {
                int n0 = wn * 32 + nt * 8 + r;
                bf[nt][0] = Bs[(kk + c) * 72 + n0];
                bf[nt][1] = Bs[(kk + c + 4) * 72 + n0];
            }
            #pragma unroll
            for (int mt = 0; mt < 2; mt++)
                #pragma unroll
                for (int nt = 0; nt < 4; nt++)
                    mma8(acc[mt][nt], af[mt], bf[nt]);
        }
    };

    ldg(0);
    sts();
    __syncthreads();
    for (int t = 1; t < 8; t++) {
        ldg(t * 32);       // prefetch next tile while computing current
        compute();
        __syncthreads();
        sts();
        __syncthreads();
    }
    compute();

    // epilogue
    #pragma unroll
    for (int mt = 0; mt < 2; mt++) {
        int gr = row0 + wm * 32 + mt * 16 + r;
        #pragma unroll
        for (int nt = 0; nt < 4; nt++) {
            int gc = col0 + wn * 32 + nt * 8 + c * 2;
            if (gr < M)
                *(float2*)&C[(size_t)gr * N + gc] =
                    make_float2(acc[mt][nt][0], acc[mt][nt][1]);
            if (gr + 8 < M)
                *(float2*)&C[(size_t)(gr + 8) * N + gc] =
                    make_float2(acc[mt][nt][2], acc[mt][nt][3]);
        }
    }
}

// ---------------- aggregation ----------------
// out[v] = relu(dinv[v]*(dinv[v]*h[v] + sum_s dinv[s]*h[s]) + b)
template<int LAYER>
__global__ void agg_kernel(const float* __restrict__ bias,
                           const int* __restrict__ batch) {
    constexpr int DIM = (LAYER == 0) ? D1 : D2;
    const float* h = (LAYER == 0) ? (const float*)g_h1 : (const float*)g_h2;
    int w    = (blockIdx.x * blockDim.x + threadIdx.x) >> 5;
    int lane = threadIdx.x & 31;
    if (w >= N_NODES) return;
    constexpr int R = DIM / 32;
    float dv = g_dinv[w];
    float acc[R];
    const float* hv = h + (size_t)w * DIM;
    #pragma unroll
    for (int j = 0; j < R; j++) acc[j] = dv * hv[j * 32 + lane];
    int e0 = g_rowstart[w], e1 = g_rowstart[w + 1];
    for (int e = e0; e < e1; e++) {
        int s = g_csrsrc[e];
        float ws = g_dinv[s];
        const float* hs = h + (size_t)s * DIM;
        #pragma unroll
        for (int j = 0; j < R; j++) acc[j] += ws * hs[j * 32 + lane];
    }
    if (LAYER == 1) {
        int g = batch[w];
        #pragma unroll
        for (int j = 0; j < R; j++) {
            float v = fmaxf(dv * acc[j] + bias[j * 32 + lane], 0.0f);
            atomicAdd(&g_pool[g * DIM + j * 32 + lane], v);
        }
        if (lane == 0) atomicAdd(&g_pcnt[g], 1.0f);
    } else {
        #pragma unroll
        for (int j = 0; j < R; j++) {
            float v = fmaxf(dv * acc[j] + bias[j * 32 + lane], 0.0f);
            g_a1[(size_t)w * DIM + j * 32 + lane] = v;
        }
    }
}

// ---------------- MLP head ----------------
__global__ void k_head(const float* __restrict__ Wl1, const float* __restrict__ bl1,
                       const float* __restrict__ Wl2, const float* __restrict__ bl2,
                       float* __restrict__ out) {
    __shared__ float gv[128];
    __shared__ float hid[64];
    int g = blockIdx.x, t = threadIdx.x;
    float cgt = fmaxf(g_pcnt[g], 1.0f);
    gv[t] = g_pool[g * D2 + t] / cgt;
    __syncthreads();
    if (t < 64) {
        float s = bl1[t];
        #pragma unroll 4
        for (int k = 0; k < 128; k++) s += gv[k] * Wl1[k * 64 + t];
        hid[t] = fmaxf(s, 0.0f);
    }
    __syncthreads();
    if (t == 0) {
        float s = bl2[0];
        #pragma unroll 4
        for (int k = 0; k < 64; k++) s += hid[k] * Wl2[k];
        out[g] = 1.0f / (1.0f + expf(-s));
    }
}

// ---------------- launch ----------------
extern "C" void kernel_launch(void* const* d_in, const int* in_sizes, int n_in,
                              void* d_out, int out_size) {
    const float* x    = (const float*)d_in[0];
    const int*   ei   = (const int*)d_in[1];
    const int*   bat  = (const int*)d_in[2];
    const float* W1   = (const float*)d_in[3];
    const float* b1   = (const float*)d_in[4];
    const float* W2   = (const float*)d_in[5];
    const float* b2   = (const float*)d_in[6];
    const float* Wl1  = (const float*)d_in[7];
    const float* bl1  = (const float*)d_in[8];
    const float* Wl2  = (const float*)d_in[9];
    const float* bl2  = (const float*)d_in[10];
    float* out = (float*)d_out;

    k_init<<<(N_NODES + 255) / 256, 256>>>();
    k_cnt<<<(N_EDGES + 255) / 256, 256>>>(ei);
    k_scan2<<<1, 1024>>>();
    k_fill<<<(N_EDGES + 255) / 256, 256>>>(ei);

    // layer 1: h1 = x @ W1 ; a1 = relu(Ahat h1 + b1)
    {
        dim3 grid((N_NODES + 127) / 128, D1 / 64);
        gemm_tc<0><<<grid, 256>>>(x, W1);
    }
    agg_kernel<0><<<(N_NODES * 32 + 255) / 256, 256>>>(b1, nullptr);

    // layer 2: h2 = a1 @ W2 ; pool(relu(Ahat h2 + b2))
    {
        dim3 grid((N_NODES + 127) / 128, D2 / 64);
        gemm_tc<1><<<grid, 256>>>(nullptr, W2);
    }
    agg_kernel<1><<<(N_NODES * 32 + 255) / 256, 256>>>(b2, bat);

    k_head<<<NUM_G, 128>>>(Wl1, bl1, Wl2, bl2, out);
}

// round 6
// speedup vs baseline: 1.8038x; 1.0563x over previous
#include <cuda_runtime.h>
#include <math.h>
#include <stdint.h>

#define N_NODES  20000
#define N_EDGES  320000
#define NUM_G    64
#define D1       256
#define D2       128

// ---------------- scratch (device globals) -------------
__device__ float g_dinv[N_NODES];
__device__ int   g_cnt[N_NODES];
__device__ int   g_cursor[N_NODES];
__device__ int   g_rowstart[N_NODES + 1];
__device__ int   g_csrsrc[N_EDGES];
__device__ float g_h1[(size_t)N_NODES * D1];   // dinv * (x @ W1)   (pre-scaled)
__device__ float g_a1[(size_t)N_NODES * D1];   // relu(Ahat h1 + b1)
__device__ float g_h2[(size_t)N_NODES * D2];   // dinv * (a1 @ W2)  (pre-scaled)
__device__ float g_pool[NUM_G * D2];
__device__ float g_pcnt[NUM_G];

// ---------------- init ----------------
__global__ void k_init() {
    int i = blockIdx.x * blockDim.x + threadIdx.x;
    if (i < N_NODES) { g_cnt[i] = 0; g_cursor[i] = 0; }
    if (i < NUM_G * D2) g_pool[i] = 0.0f;
    if (i < NUM_G) g_pcnt[i] = 0.0f;
}

// ---------------- degree histogram over dst ----------------
__global__ void k_cnt(const int* __restrict__ ei) {
    int e = blockIdx.x * blockDim.x + threadIdx.x;
    if (e < N_EDGES) atomicAdd(&g_cnt[ei[N_EDGES + e]], 1);
}

__global__ void k_dinv() {
    int i = blockIdx.x * blockDim.x + threadIdx.x;
    if (i < N_NODES) g_dinv[i] = rsqrtf((float)(g_cnt[i] + 1));  // +1 self loop
}

// ---------------- fast single-pass scan ----------------
__global__ __launch_bounds__(1024) void k_scan2() {
    constexpr int PER = 20;  // 1024*20 = 20480 >= 20000
    __shared__ int wsum[32];
    int tid = threadIdx.x, lane = tid & 31, wid = tid >> 5;
    int base = tid * PER;
    int v[PER];
    int s = 0;
    #pragma unroll
    for (int j = 0; j < PER; j++) {
        int i = base + j;
        int c = (i < N_NODES) ? g_cnt[i] : 0;
        v[j] = s;
        s += c;
    }
    int incl = s;
    #pragma unroll
    for (int off = 1; off < 32; off <<= 1) {
        int n = __shfl_up_sync(0xffffffffu, incl, off);
        if (lane >= off) incl += n;
    }
    if (lane == 31) wsum[wid] = incl;
    __syncthreads();
    if (wid == 0) {
        int w = wsum[lane];
        #pragma unroll
        for (int off = 1; off < 32; off <<= 1) {
            int n = __shfl_up_sync(0xffffffffu, w, off);
            if (lane >= off) w += n;
        }
        wsum[lane] = w;
    }
    __syncthreads();
    int warpbase = (wid > 0) ? wsum[wid - 1] : 0;
    int thbase = warpbase + incl - s;
    #pragma unroll
    for (int j = 0; j < PER; j++) {
        int i = base + j;
        if (i < N_NODES) g_rowstart[i] = thbase + v[j];
    }
    if (tid == 0) g_rowstart[N_NODES] = N_EDGES;
}

// ---------------- CSR fill ----------------
__global__ void k_fill(const int* __restrict__ ei) {
    int e = blockIdx.x * blockDim.x + threadIdx.x;
    if (e < N_EDGES) {
        int d = ei[N_EDGES + e];
        int pos = atomicAdd(&g_cursor[d], 1);
        g_csrsrc[g_rowstart[d] + pos] = ei[e];
    }
}

// ---------------- tf32 tensor-core GEMM, epilogue scales rows by dinv -------
__device__ __forceinline__ uint32_t f2tf32(float f) {
    uint32_t u;
    asm("cvt.rna.tf32.f32 %0, %1;" : "=r"(u) : "f"(f));
    return u;
}
__device__ __forceinline__ void mma8(float* acc, const uint32_t* a, const uint32_t* b) {
    asm volatile(
        "mma.sync.aligned.m16n8k8.row.col.f32.tf32.tf32.f32 "
        "{%0,%1,%2,%3},{%4,%5,%6,%7},{%8,%9},{%0,%1,%2,%3};"
        : "+f"(acc[0]), "+f"(acc[1]), "+f"(acc[2]), "+f"(acc[3])
        : "r"(a[0]), "r"(a[1]), "r"(a[2]), "r"(a[3]), "r"(b[0]), "r"(b[1]));
}

// C[M,N] = dinv[row] * (A[M,256] @ B[256,N]). BM=128, BN=64, BK=32, 256 thr.
template<int LAYER>
__global__ __launch_bounds__(256) void gemm_tc(const float* __restrict__ Ain,
                                               const float* __restrict__ Bw) {
    constexpr int K = 256;
    constexpr int N = (LAYER == 0) ? 256 : 128;
    constexpr int M = N_NODES;
    const float* A = (LAYER == 0) ? Ain : (const float*)g_a1;
    float* C = (LAYER == 0) ? (float*)g_h1 : (float*)g_h2;

    __shared__ uint32_t As[128 * 36];
    __shared__ uint32_t Bs[32 * 72];

    int tid = threadIdx.x, lane = tid & 31, warp = tid >> 5;
    int wm = warp & 3, wn = warp >> 2;
    int row0 = blockIdx.x * 128, col0 = blockIdx.y * 64;

    int am = tid >> 1, ah = (tid & 1) * 16;
    int bk = tid >> 4, bn = (tid & 15) * 4;

    float acc[2][4][4];
    #pragma unroll
    for (int mt = 0; mt < 2; mt++)
        #pragma unroll
        for (int nt = 0; nt < 4; nt++)
            #pragma unroll
            for (int i = 0; i < 4; i++) acc[mt][nt][i] = 0.0f;

    float4 areg[4];
    float4 breg[2];
    bool aok = (row0 + am) < M;
    const float* aptr = A + (size_t)(row0 + am) * K + ah;
    const float* bptr = Bw + (size_t)bk * N + col0 + bn;

    auto ldg = [&](int k0) {
        #pragma unroll
        for (int j = 0; j < 4; j++)
            areg[j] = aok ? *(const float4*)(aptr + k0 + 4 * j)
                          : make_float4(0.f, 0.f, 0.f, 0.f);
        breg[0] = *(const float4*)(bptr + (size_t)k0 * N);
        breg[1] = *(const float4*)(bptr + (size_t)(k0 + 16) * N);
    };
    auto sts = [&]() {
        #pragma unroll
        for (int j = 0; j < 4; j++) {
            uint4 u = make_uint4(f2tf32(areg[j].x), f2tf32(areg[j].y),
                                 f2tf32(areg[j].z), f2tf32(areg[j].w));
            *(uint4*)&As[am * 36 + ah + 4 * j] = u;
        }
        uint4 u0 = make_uint4(f2tf32(breg[0].x), f2tf32(breg[0].y),
                              f2tf32(breg[0].z), f2tf32(breg[0].w));
        uint4 u1 = make_uint4(f2tf32(breg[1].x), f2tf32(breg[1].y),
                              f2tf32(breg[1].z), f2tf32(breg[1].w));
        *(uint4*)&Bs[bk * 72 + bn] = u0;
        *(uint4*)&Bs[(bk + 16) * 72 + bn] = u1;
    };
    int r = lane >> 2, c = lane & 3;
    auto compute = [&]() {
        #pragma unroll
        for (int kk = 0; kk < 32; kk += 8) {
            uint32_t af[2][4], bf[4][2];
            #pragma unroll
            for (int mt = 0; mt < 2; mt++) {
                int m0 = wm * 32 + mt * 16 + r;
                af[mt][0] = As[m0 * 36 + kk + c];
                af[mt][1] = As[(m0 + 8) * 36 + kk + c];
                af[mt][2] = As[m0 * 36 + kk + c + 4];
                af[mt][3] = As[(m0 + 8) * 36 + kk + c + 4];
            }
            #pragma unroll
            for (int nt = 0; nt < 4; nt++) {
                int n0 = wn * 32 + nt * 8 + r;
                bf[nt][0] = Bs[(kk + c) * 72 + n0];
                bf[nt][1] = Bs[(kk + c + 4) * 72 + n0];
            }
            #pragma unroll
            for (int mt = 0; mt < 2; mt++)
                #pragma unroll
                for (int nt = 0; nt < 4; nt++)
                    mma8(acc[mt][nt], af[mt], bf[nt]);
        }
    };

    ldg(0);
    sts();
    __syncthreads();
    for (int t = 1; t < 8; t++) {
        ldg(t * 32);
        compute();
        __syncthreads();
        sts();
        __syncthreads();
    }
    compute();

    // epilogue: scale rows by dinv
    #pragma unroll
    for (int mt = 0; mt < 2; mt++) {
        int gr = row0 + wm * 32 + mt * 16 + r;
        bool ok0 = gr < M, ok1 = (gr + 8) < M;
        float dv0 = ok0 ? g_dinv[gr] : 0.0f;
        float dv1 = ok1 ? g_dinv[gr + 8] : 0.0f;
        #pragma unroll
        for (int nt = 0; nt < 4; nt++) {
            int gc = col0 + wn * 32 + nt * 8 + c * 2;
            if (ok0)
                *(float2*)&C[(size_t)gr * N + gc] =
                    make_float2(acc[mt][nt][0] * dv0, acc[mt][nt][1] * dv0);
            if (ok1)
                *(float2*)&C[(size_t)(gr + 8) * N + gc] =
                    make_float2(acc[mt][nt][2] * dv1, acc[mt][nt][3] * dv1);
        }
    }
}

// ---------------- aggregation (h rows pre-scaled by dinv) ----------------
// out[v] = relu(dinv[v] * (h[v] + sum_{s in N(v)} h[s]) + b)
__device__ __forceinline__ float4 f4add(float4 a, float4 b) {
    return make_float4(a.x + b.x, a.y + b.y, a.z + b.z, a.w + b.w);
}
template<int LAYER>
__global__ void agg_kernel(const float* __restrict__ bias,
                           const int* __restrict__ batch) {
    constexpr int DIM = (LAYER == 0) ? D1 : D2;
    constexpr int R = DIM / 128;            // float4 regs per lane
    const float4* h = (const float4*)((LAYER == 0) ? g_h1 : g_h2);
    int w    = (blockIdx.x * blockDim.x + threadIdx.x) >> 5;
    int lane = threadIdx.x & 31;
    if (w >= N_NODES) return;
    constexpr int RV = DIM / 4;             // float4 per row
    float dv = g_dinv[w];
    float4 acc[R];
    const float4* hv = h + (size_t)w * RV;
    #pragma unroll
    for (int j = 0; j < R; j++) acc[j] = hv[j * 32 + lane];   // self term
    int e0 = g_rowstart[w], e1 = g_rowstart[w + 1];
    int e = e0;
    for (; e + 4 <= e1; e += 4) {
        int s0 = g_csrsrc[e], s1 = g_csrsrc[e + 1];
        int s2 = g_csrsrc[e + 2], s3 = g_csrsrc[e + 3];
        const float4* p0 = h + (size_t)s0 * RV;
        const float4* p1 = h + (size_t)s1 * RV;
        const float4* p2 = h + (size_t)s2 * RV;
        const float4* p3 = h + (size_t)s3 * RV;
        #pragma unroll
        for (int j = 0; j < R; j++) {
            float4 v0 = p0[j * 32 + lane];
            float4 v1 = p1[j * 32 + lane];
            float4 v2 = p2[j * 32 + lane];
            float4 v3 = p3[j * 32 + lane];
            acc[j] = f4add(acc[j], f4add(f4add(v0, v1), f4add(v2, v3)));
        }
    }
    for (; e < e1; e++) {
        int s = g_csrsrc[e];
        const float4* p = h + (size_t)s * RV;
        #pragma unroll
        for (int j = 0; j < R; j++) acc[j] = f4add(acc[j], p[j * 32 + lane]);
    }
    const float4* b4 = (const float4*)bias;
    if (LAYER == 1) {
        int g = batch[w];
        #pragma unroll
        for (int j = 0; j < R; j++) {
            float4 b = b4[j * 32 + lane];
            float vx = fmaxf(dv * acc[j].x + b.x, 0.0f);
            float vy = fmaxf(dv * acc[j].y + b.y, 0.0f);
            float vz = fmaxf(dv * acc[j].z + b.z, 0.0f);
            float vw = fmaxf(dv * acc[j].w + b.w, 0.0f);
            int o = g * DIM + (j * 32 + lane) * 4;
            atomicAdd(&g_pool[o + 0], vx);
            atomicAdd(&g_pool[o + 1], vy);
            atomicAdd(&g_pool[o + 2], vz);
            atomicAdd(&g_pool[o + 3], vw);
        }
        if (lane == 0) atomicAdd(&g_pcnt[g], 1.0f);
    } else {
        float4* out4 = (float4*)g_a1;
        #pragma unroll
        for (int j = 0; j < R; j++) {
            float4 b = b4[j * 32 + lane];
            float4 v;
            v.x = fmaxf(dv * acc[j].x + b.x, 0.0f);
            v.y = fmaxf(dv * acc[j].y + b.y, 0.0f);
            v.z = fmaxf(dv * acc[j].z + b.z, 0.0f);
            v.w = fmaxf(dv * acc[j].w + b.w, 0.0f);
            out4[(size_t)w * RV + j * 32 + lane] = v;
        }
    }
}

// ---------------- MLP head ----------------
__global__ void k_head(const float* __restrict__ Wl1, const float* __restrict__ bl1,
                       const float* __restrict__ Wl2, const float* __restrict__ bl2,
                       float* __restrict__ out) {
    __shared__ float gv[128];
    __shared__ float hid[64];
    int g = blockIdx.x, t = threadIdx.x;
    float cgt = fmaxf(g_pcnt[g], 1.0f);
    gv[t] = g_pool[g * D2 + t] / cgt;
    __syncthreads();
    if (t < 64) {
        float s = bl1[t];
        #pragma unroll 4
        for (int k = 0; k < 128; k++) s += gv[k] * Wl1[k * 64 + t];
        hid[t] = fmaxf(s, 0.0f);
    }
    __syncthreads();
    if (t == 0) {
        float s = bl2[0];
        #pragma unroll 4
        for (int k = 0; k < 64; k++) s += hid[k] * Wl2[k];
        out[g] = 1.0f / (1.0f + expf(-s));
    }
}

// ---------------- launch ----------------
extern "C" void kernel_launch(void* const* d_in, const int* in_sizes, int n_in,
                              void* d_out, int out_size) {
    const float* x    = (const float*)d_in[0];
    const int*   ei   = (const int*)d_in[1];
    const int*   bat  = (const int*)d_in[2];
    const float* W1   = (const float*)d_in[3];
    const float* b1   = (const float*)d_in[4];
    const float* W2   = (const float*)d_in[5];
    const float* b2   = (const float*)d_in[6];
    const float* Wl1  = (const float*)d_in[7];
    const float* bl1  = (const float*)d_in[8];
    const float* Wl2  = (const float*)d_in[9];
    const float* bl2  = (const float*)d_in[10];
    float* out = (float*)d_out;

    // fork a side stream inside the captured graph for the CSR build
    cudaStream_t s1;
    cudaEvent_t evA, evDinv, evCsr;
    cudaStreamCreateWithFlags(&s1, cudaStreamNonBlocking);
    cudaEventCreateWithFlags(&evA,    cudaEventDisableTiming);
    cudaEventCreateWithFlags(&evDinv, cudaEventDisableTiming);
    cudaEventCreateWithFlags(&evCsr,  cudaEventDisableTiming);

    cudaEventRecord(evA, 0);
    cudaStreamWaitEvent(s1, evA, 0);

    // side branch: CSR preprocessing
    k_init<<<(N_NODES + 255) / 256, 256, 0, s1>>>();
    k_cnt<<<(N_EDGES + 255) / 256, 256, 0, s1>>>(ei);
    k_dinv<<<(N_NODES + 255) / 256, 256, 0, s1>>>();
    cudaEventRecord(evDinv, s1);
    k_scan2<<<1, 1024, 0, s1>>>();
    k_fill<<<(N_EDGES + 255) / 256, 256, 0, s1>>>(ei);
    cudaEventRecord(evCsr, s1);

    // main branch: gemm1 needs dinv for its epilogue
    cudaStreamWaitEvent(0, evDinv, 0);
    {
        dim3 grid((N_NODES + 127) / 128, D1 / 64);
        gemm_tc<0><<<grid, 256>>>(x, W1);
    }
    cudaStreamWaitEvent(0, evCsr, 0);   // join CSR branch before aggregation
    agg_kernel<0><<<(N_NODES * 32 + 255) / 256, 256>>>(b1, nullptr);

    {
        dim3 grid((N_NODES + 127) / 128, D2 / 64);
        gemm_tc<1><<<grid, 256>>>(nullptr, W2);
    }
    agg_kernel<1><<<(N_NODES * 32 + 255) / 256, 256>>>(b2, bat);

    k_head<<<NUM_G, 128>>>(Wl1, bl1, Wl2, bl2, out);
}

// round 7
// speedup vs baseline: 1.9943x; 1.1057x over previous
#include <cuda_runtime.h>
#include <math.h>
#include <stdint.h>

#define N_NODES  20000
#define N_EDGES  320000
#define NUM_G    64
#define D1       256
#define D2       128

// ---------------- scratch (device globals) -------------
__device__ float g_dinv[N_NODES];
__device__ int   g_cnt[N_NODES];
__device__ int   g_cursor[N_NODES];
__device__ int   g_rowstart[N_NODES + 1];
__device__ int   g_csrsrc[N_EDGES];
__device__ uint4 g_h1b[(size_t)N_NODES * (D1 / 8)];  // bf16x2-packed dinv*(x@W1)
__device__ float g_a1[(size_t)N_NODES * D1];         // relu(Ahat h1 + b1), fp32
__device__ uint2 g_h2b[(size_t)N_NODES * (D2 / 4)];  // bf16x2-packed dinv*(a1@W2)
__device__ float g_pool[NUM_G * D2];
__device__ float g_pcnt[NUM_G];

// ---------------- helpers ----------------
__device__ __forceinline__ uint32_t f2tf32(float f) {
    uint32_t u;
    asm("cvt.rna.tf32.f32 %0, %1;" : "=r"(u) : "f"(f));
    return u;
}
__device__ __forceinline__ uint32_t f2bf2(float lo, float hi) {
    uint32_t r;
    asm("cvt.rn.bf16x2.f32 %0, %1, %2;" : "=r"(r) : "f"(hi), "f"(lo));
    return r;
}
__device__ __forceinline__ void addbf2(float* a, uint32_t u) {
    a[0] += __uint_as_float(u << 16);
    a[1] += __uint_as_float(u & 0xffff0000u);
}

// ---------------- init ----------------
__global__ void k_init() {
    int i = blockIdx.x * blockDim.x + threadIdx.x;
    if (i < N_NODES) { g_cnt[i] = 0; g_cursor[i] = 0; }
    if (i < NUM_G * D2) g_pool[i] = 0.0f;
    if (i < NUM_G) g_pcnt[i] = 0.0f;
}

// ---------------- degree histogram over dst (x4 vectorized) ----------------
__global__ void k_cnt(const int* __restrict__ ei) {
    int t = blockIdx.x * blockDim.x + threadIdx.x;
    if (t < N_EDGES / 4) {
        int4 d = ((const int4*)(ei + N_EDGES))[t];
        atomicAdd(&g_cnt[d.x], 1);
        atomicAdd(&g_cnt[d.y], 1);
        atomicAdd(&g_cnt[d.z], 1);
        atomicAdd(&g_cnt[d.w], 1);
    }
}

__global__ void k_dinv() {
    int i = blockIdx.x * blockDim.x + threadIdx.x;
    if (i < N_NODES) g_dinv[i] = rsqrtf((float)(g_cnt[i] + 1));  // +1 self loop
}

// ---------------- coalesced single-pass scan (smem staged) ----------------
__global__ __launch_bounds__(1024) void k_scan2() {
    extern __shared__ int stage[];     // N_NODES ints (80KB dynamic)
    __shared__ int wsum[32];
    constexpr int PER = 20;            // 1024*20 >= 20000
    int tid = threadIdx.x, lane = tid & 31, wid = tid >> 5;
    for (int i = tid; i < N_NODES; i += 1024) stage[i] = g_cnt[i];
    __syncthreads();
    int base = tid * PER;
    int v[PER];
    int s = 0;
    #pragma unroll
    for (int j = 0; j < PER; j++) {
        int i = base + j;
        int c = (i < N_NODES) ? stage[i] : 0;
        v[j] = s;
        s += c;
    }
    int incl = s;
    #pragma unroll
    for (int off = 1; off < 32; off <<= 1) {
        int n = __shfl_up_sync(0xffffffffu, incl, off);
        if (lane >= off) incl += n;
    }
    if (lane == 31) wsum[wid] = incl;
    __syncthreads();
    if (wid == 0) {
        int w = wsum[lane];
        #pragma unroll
        for (int off = 1; off < 32; off <<= 1) {
            int n = __shfl_up_sync(0xffffffffu, w, off);
            if (lane >= off) w += n;
        }
        wsum[lane] = w;
    }
    __syncthreads();
    int warpbase = (wid > 0) ? wsum[wid - 1] : 0;
    int thbase = warpbase + incl - s;
    #pragma unroll
    for (int j = 0; j < PER; j++) {
        int i = base + j;
        if (i < N_NODES) g_rowstart[i] = thbase + v[j];
    }
    if (tid == 0) g_rowstart[N_NODES] = N_EDGES;
}

// ---------------- CSR fill ----------------
__global__ void k_fill(const int* __restrict__ ei) {
    int e = blockIdx.x * blockDim.x + threadIdx.x;
    if (e < N_EDGES) {
        int d = ei[N_EDGES + e];
        int pos = atomicAdd(&g_cursor[d], 1);
        g_csrsrc[g_rowstart[d] + pos] = ei[e];
    }
}

// ---------------- tf32 tensor-core GEMM; epilogue: *dinv, pack bf16x2 -------
__device__ __forceinline__ void mma8(float* acc, const uint32_t* a, const uint32_t* b) {
    asm volatile(
        "mma.sync.aligned.m16n8k8.row.col.f32.tf32.tf32.f32 "
        "{%0,%1,%2,%3},{%4,%5,%6,%7},{%8,%9},{%0,%1,%2,%3};"
        : "+f"(acc[0]), "+f"(acc[1]), "+f"(acc[2]), "+f"(acc[3])
        : "r"(a[0]), "r"(a[1]), "r"(a[2]), "r"(a[3]), "r"(b[0]), "r"(b[1]));
}

// C_bf16[M,N] = dinv[row] * (A[M,256] @ B[256,N]). BM=128, BN=64, BK=32.
template<int LAYER>
__global__ __launch_bounds__(256) void gemm_tc(const float* __restrict__ Ain,
                                               const float* __restrict__ Bw) {
    constexpr int K = 256;
    constexpr int N = (LAYER == 0) ? 256 : 128;
    constexpr int M = N_NODES;
    const float* A = (LAYER == 0) ? Ain : (const float*)g_a1;
    uint32_t* C = (LAYER == 0) ? (uint32_t*)g_h1b : (uint32_t*)g_h2b;

    __shared__ uint32_t As[128 * 36];
    __shared__ uint32_t Bs[32 * 72];

    int tid = threadIdx.x, lane = tid & 31, warp = tid >> 5;
    int wm = warp & 3, wn = warp >> 2;
    int row0 = blockIdx.x * 128, col0 = blockIdx.y * 64;

    int am = tid >> 1, ah = (tid & 1) * 16;
    int bk = tid >> 4, bn = (tid & 15) * 4;

    float acc[2][4][4];
    #pragma unroll
    for (int mt = 0; mt < 2; mt++)
        #pragma unroll
        for (int nt = 0; nt < 4; nt++)
            #pragma unroll
            for (int i = 0; i < 4; i++) acc[mt][nt][i] = 0.0f;

    float4 areg[4];
    float4 breg[2];
    bool aok = (row0 + am) < M;
    const float* aptr = A + (size_t)(row0 + am) * K + ah;
    const float* bptr = Bw + (size_t)bk * N + col0 + bn;

    auto ldg = [&](int k0) {
        #pragma unroll
        for (int j = 0; j < 4; j++)
            areg[j] = aok ? *(const float4*)(aptr + k0 + 4 * j)
                          : make_float4(0.f, 0.f, 0.f, 0.f);
        breg[0] = *(const float4*)(bptr + (size_t)k0 * N);
        breg[1] = *(const float4*)(bptr + (size_t)(k0 + 16) * N);
    };
    auto sts = [&]() {
        #pragma unroll
        for (int j = 0; j < 4; j++) {
            uint4 u = make_uint4(f2tf32(areg[j].x), f2tf32(areg[j].y),
                                 f2tf32(areg[j].z), f2tf32(areg[j].w));
            *(uint4*)&As[am * 36 + ah + 4 * j] = u;
        }
        uint4 u0 = make_uint4(f2tf32(breg[0].x), f2tf32(breg[0].y),
                              f2tf32(breg[0].z), f2tf32(breg[0].w));
        uint4 u1 = make_uint4(f2tf32(breg[1].x), f2tf32(breg[1].y),
                              f2tf32(breg[1].z), f2tf32(breg[1].w));
        *(uint4*)&Bs[bk * 72 + bn] = u0;
        *(uint4*)&Bs[(bk + 16) * 72 + bn] = u1;
    };
    int r = lane >> 2, c = lane & 3;
    auto compute = [&]() {
        #pragma unroll
        for (int kk = 0; kk < 32; kk += 8) {
            uint32_t af[2][4], bf[4][2];
            #pragma unroll
            for (int mt = 0; mt < 2; mt++) {
                int m0 = wm * 32 + mt * 16 + r;
                af[mt][0] = As[m0 * 36 + kk + c];
                af[mt][1] = As[(m0 + 8) * 36 + kk + c];
                af[mt][2] = As[m0 * 36 + kk + c + 4];
                af[mt][3] = As[(m0 + 8) * 36 + kk + c + 4];
            }
            #pragma unroll
            for (int nt = 0; nt < 4; nt++) {
                int n0 = wn * 32 + nt * 8 + r;
                bf[nt][0] = Bs[(kk + c) * 72 + n0];
                bf[nt][1] = Bs[(kk + c + 4) * 72 + n0];
            }
            #pragma unroll
            for (int mt = 0; mt < 2; mt++)
                #pragma unroll
                for (int nt = 0; nt < 4; nt++)
                    mma8(acc[mt][nt], af[mt], bf[nt]);
        }
    };

    ldg(0);
    sts();
    __syncthreads();
    for (int t = 1; t < 8; t++) {
        ldg(t * 32);
        compute();
        __syncthreads();
        sts();
        __syncthreads();
    }
    compute();

    // epilogue: scale rows by dinv, pack to bf16x2
    constexpr int NU = N / 2;  // uint32 per row
    #pragma unroll
    for (int mt = 0; mt < 2; mt++) {
        int gr = row0 + wm * 32 + mt * 16 + r;
        bool ok0 = gr < M, ok1 = (gr + 8) < M;
        float dv0 = ok0 ? g_dinv[gr] : 0.0f;
        float dv1 = ok1 ? g_dinv[gr + 8] : 0.0f;
        #pragma unroll
        for (int nt = 0; nt < 4; nt++) {
            int gcu = (col0 + wn * 32 + nt * 8) / 2 + c;
            if (ok0)
                C[(size_t)gr * NU + gcu] =
                    f2bf2(acc[mt][nt][0] * dv0, acc[mt][nt][1] * dv0);
            if (ok1)
                C[(size_t)(gr + 8) * NU + gcu] =
                    f2bf2(acc[mt][nt][2] * dv1, acc[mt][nt][3] * dv1);
        }
    }
}

// ---------------- aggregation over bf16-packed h ----------------
// out[v] = relu(dinv[v] * (h[v] + sum_{s in N(v)} h[s]) + b)
// LAYER 0: lane loads uint4 (8 bf16) -> acc[8]; output g_a1 fp32.
// LAYER 1: lane loads uint2 (4 bf16) -> acc[4]; fused mean-pool atomics.
template<int LAYER>
__global__ void agg_kernel(const float* __restrict__ bias,
                           const int* __restrict__ batch) {
    constexpr int DIM = (LAYER == 0) ? D1 : D2;
    constexpr int NA = (LAYER == 0) ? 8 : 4;   // floats per lane
    int w    = (blockIdx.x * blockDim.x + threadIdx.x) >> 5;
    int lane = threadIdx.x & 31;
    if (w >= N_NODES) return;
    float dv = g_dinv[w];
    float acc[NA];
    #pragma unroll
    for (int j = 0; j < NA; j++) acc[j] = 0.0f;

    if (LAYER == 0) {
        const uint4* h = (const uint4*)g_h1b;
        uint4 u = h[(size_t)w * 32 + lane];      // self term
        addbf2(acc + 0, u.x); addbf2(acc + 2, u.y);
        addbf2(acc + 4, u.z); addbf2(acc + 6, u.w);
        int e0 = g_rowstart[w], e1 = g_rowstart[w + 1];
        int e = e0;
        for (; e + 4 <= e1; e += 4) {
            int s0 = g_csrsrc[e], s1 = g_csrsrc[e + 1];
            int s2 = g_csrsrc[e + 2], s3 = g_csrsrc[e + 3];
            uint4 u0 = h[(size_t)s0 * 32 + lane];
            uint4 u1 = h[(size_t)s1 * 32 + lane];
            uint4 u2 = h[(size_t)s2 * 32 + lane];
            uint4 u3 = h[(size_t)s3 * 32 + lane];
            addbf2(acc + 0, u0.x); addbf2(acc + 2, u0.y);
            addbf2(acc + 4, u0.z); addbf2(acc + 6, u0.w);
            addbf2(acc + 0, u1.x); addbf2(acc + 2, u1.y);
            addbf2(acc + 4, u1.z); addbf2(acc + 6, u1.w);
            addbf2(acc + 0, u2.x); addbf2(acc + 2, u2.y);
            addbf2(acc + 4, u2.z); addbf2(acc + 6, u2.w);
            addbf2(acc + 0, u3.x); addbf2(acc + 2, u3.y);
            addbf2(acc + 4, u3.z); addbf2(acc + 6, u3.w);
        }
        for (; e < e1; e++) {
            uint4 uu = h[(size_t)g_csrsrc[e] * 32 + lane];
            addbf2(acc + 0, uu.x); addbf2(acc + 2, uu.y);
            addbf2(acc + 4, uu.z); addbf2(acc + 6, uu.w);
        }
        // epilogue: relu(dv*acc + b) -> g_a1 fp32
        float o[8];
        #pragma unroll
        for (int j = 0; j < 8; j++)
            o[j] = fmaxf(dv * acc[j] + bias[lane * 8 + j], 0.0f);
        float4* dst = (float4*)(g_a1 + (size_t)w * D1 + lane * 8);
        dst[0] = make_float4(o[0], o[1], o[2], o[3]);
        dst[1] = make_float4(o[4], o[5], o[6], o[7]);
    } else {
        const uint2* h = (const uint2*)g_h2b;
        uint2 u = h[(size_t)w * 32 + lane];
        addbf2(acc + 0, u.x); addbf2(acc + 2, u.y);
        int e0 = g_rowstart[w], e1 = g_rowstart[w + 1];
        int e = e0;
        for (; e + 4 <= e1; e += 4) {
            int s0 = g_csrsrc[e], s1 = g_csrsrc[e + 1];
            int s2 = g_csrsrc[e + 2], s3 = g_csrsrc[e + 3];
            uint2 u0 = h[(size_t)s0 * 32 + lane];
            uint2 u1 = h[(size_t)s1 * 32 + lane];
            uint2 u2 = h[(size_t)s2 * 32 + lane];
            uint2 u3 = h[(size_t)s3 * 32 + lane];
            addbf2(acc + 0, u0.x); addbf2(acc + 2, u0.y);
            addbf2(acc + 0, u1.x); addbf2(acc + 2, u1.y);
            addbf2(acc + 0, u2.x); addbf2(acc + 2, u2.y);
            addbf2(acc + 0, u3.x); addbf2(acc + 2, u3.y);
        }
        for (; e < e1; e++) {
            uint2 uu = h[(size_t)g_csrsrc[e] * 32 + lane];
            addbf2(acc + 0, uu.x); addbf2(acc + 2, uu.y);
        }
        int g = batch[w];
        #pragma unroll
        for (int j = 0; j < 4; j++) {
            float v = fmaxf(dv * acc[j] + bias[lane * 4 + j], 0.0f);
            atomicAdd(&g_pool[g * D2 + lane * 4 + j], v);
        }
        if (lane == 0) atomicAdd(&g_pcnt[g], 1.0f);
    }
}

// ---------------- MLP head ----------------
__global__ void k_head(const float* __restrict__ Wl1, const float* __restrict__ bl1,
                       const float* __restrict__ Wl2, const float* __restrict__ bl2,
                       float* __restrict__ out) {
    __shared__ float gv[128];
    __shared__ float hid[64];
    int g = blockIdx.x, t = threadIdx.x;
    float cgt = fmaxf(g_pcnt[g], 1.0f);
    gv[t] = g_pool[g * D2 + t] / cgt;
    __syncthreads();
    if (t < 64) {
        float s = bl1[t];
        #pragma unroll 4
        for (int k = 0; k < 128; k++) s += gv[k] * Wl1[k * 64 + t];
        hid[t] = fmaxf(s, 0.0f);
    }
    __syncthreads();
    if (t == 0) {
        float s = bl2[0];
        #pragma unroll 4
        for (int k = 0; k < 64; k++) s += hid[k] * Wl2[k];
        out[g] = 1.0f / (1.0f + expf(-s));
    }
}

// ---------------- launch ----------------
extern "C" void kernel_launch(void* const* d_in, const int* in_sizes, int n_in,
                              void* d_out, int out_size) {
    const float* x    = (const float*)d_in[0];
    const int*   ei   = (const int*)d_in[1];
    const int*   bat  = (const int*)d_in[2];
    const float* W1   = (const float*)d_in[3];
    const float* b1   = (const float*)d_in[4];
    const float* W2   = (const float*)d_in[5];
    const float* b2   = (const float*)d_in[6];
    const float* Wl1  = (const float*)d_in[7];
    const float* bl1  = (const float*)d_in[8];
    const float* Wl2  = (const float*)d_in[9];
    const float* bl2  = (const float*)d_in[10];
    float* out = (float*)d_out;

    static bool attr_set = false;
    if (!attr_set) {
        cudaFuncSetAttribute(k_scan2, cudaFuncAttributeMaxDynamicSharedMemorySize,
                             N_NODES * sizeof(int));
        attr_set = true;
    }

    cudaStream_t s1;
    cudaEvent_t evA, evDinv, evCsr;
    cudaStreamCreateWithFlags(&s1, cudaStreamNonBlocking);
    cudaEventCreateWithFlags(&evA,    cudaEventDisableTiming);
    cudaEventCreateWithFlags(&evDinv, cudaEventDisableTiming);
    cudaEventCreateWithFlags(&evCsr,  cudaEventDisableTiming);

    cudaEventRecord(evA, 0);
    cudaStreamWaitEvent(s1, evA, 0);

    // side branch: CSR preprocessing
    k_init<<<(N_NODES + 255) / 256, 256, 0, s1>>>();
    k_cnt<<<(N_EDGES / 4 + 255) / 256, 256, 0, s1>>>(ei);
    k_dinv<<<(N_NODES + 255) / 256, 256, 0, s1>>>();
    cudaEventRecord(evDinv, s1);
    k_scan2<<<1, 1024, N_NODES * sizeof(int), s1>>>();
    k_fill<<<(N_EDGES + 255) / 256, 256, 0, s1>>>(ei);
    cudaEventRecord(evCsr, s1);

    // main branch
    cudaStreamWaitEvent(0, evDinv, 0);
    {
        dim3 grid((N_NODES + 127) / 128, D1 / 64);
        gemm_tc<0><<<grid, 256>>>(x, W1);
    }
    cudaStreamWaitEvent(0, evCsr, 0);
    agg_kernel<0><<<(N_NODES * 32 + 255) / 256, 256>>>(b1, nullptr);

    {
        dim3 grid((N_NODES + 127) / 128, D2 / 64);
        gemm_tc<1><<<grid, 256>>>(nullptr, W2);
    }
    agg_kernel<1><<<(N_NODES * 32 + 255) / 256, 256>>>(b2, bat);

    k_head<<<NUM_G, 128>>>(Wl1, bl1, Wl2, bl2, out);
}